// round 2
// baseline (speedup 1.0000x reference)
#include <cuda_runtime.h>
#include <math.h>

#define NN 80000
#define NE 1280000
#define NG 512
#define FF 64

// ---------------- scratch (device globals, no allocation) ----------------
__device__ __align__(16) float g_y0[NN*FF];
__device__ __align__(16) float g_y1[NN*FF];
__device__ __align__(16) float g_yr[NN*FF];
__device__ __align__(16) float g_agg[NN*FF];
__device__ __align__(16) float g_hA[NN*FF];
__device__ __align__(16) float g_hB[NN*FF];
__device__ __align__(16) float g_deg[NN];
__device__ __align__(16) float g_pooled[NG*FF];

// ---------------- helpers ----------------
__device__ __forceinline__ void red_add_v4(float* p, float4 v) {
    asm volatile("red.global.add.v4.f32 [%0], {%1,%2,%3,%4};"
                 :: "l"(p), "f"(v.x), "f"(v.y), "f"(v.z), "f"(v.w) : "memory");
}

__device__ __forceinline__ float elu1(float v) {
    return v > 0.0f ? v : expm1f(v);
}

// ---------------- zero kernels ----------------
__global__ void k_zero_agg() {
    int t = blockIdx.x * blockDim.x + threadIdx.x;   // exactly NN*FF threads
    g_agg[t] = 0.0f;
}

__global__ void k_zero_misc() {
    int t = blockIdx.x * blockDim.x + threadIdx.x;
    if (t < NN) g_deg[t] = 0.0f;
    else if (t < NN + NG*FF) g_pooled[t - NN] = 0.0f;
}

// ---------------- degree (once per launch) ----------------
__global__ void k_deg(const int* __restrict__ dst) {
    int e = blockIdx.x * blockDim.x + threadIdx.x;   // exactly NE threads
    atomicAdd(&g_deg[dst[e]], 1.0f);
}

// ---------------- layer 1 transform: Fin=3 ----------------
__global__ void k_l1(const float* __restrict__ x, const float* __restrict__ W,
                     const float* __restrict__ root) {
    int t = blockIdx.x * blockDim.x + threadIdx.x;   // NN*FF threads exactly
    int n = t >> 6, f = t & 63;
    float x0 = x[n*3+0], x1 = x[n*3+1], x2 = x[n*3+2];
    const float* W0 = W;          // (3,64)
    const float* W1 = W + 192;    // (3,64)
    g_y0[t] = x0*W0[f]      + x1*W0[64+f]   + x2*W0[128+f];
    g_y1[t] = x0*W1[f]      + x1*W1[64+f]   + x2*W1[128+f];
    g_yr[t] = x0*root[f]    + x1*root[64+f] + x2*root[128+f];
}

// ---------------- 64x64 transform: y0 = X@W0, y1 = X@W1 ----------------
__global__ __launch_bounds__(256) void k_mm2(int xsel, const float* __restrict__ W0g,
                                             const float* __restrict__ W1g) {
    __shared__ float sW0[4096];
    __shared__ float sW1[4096];
    __shared__ float sX[16][64];
    const float* X = xsel ? g_hB : g_hA;
    for (int i = threadIdx.x; i < 4096; i += 256) { sW0[i] = W0g[i]; sW1[i] = W1g[i]; }
    int f = threadIdx.x & 63;
    int q = threadIdx.x >> 6;     // 0..3, each handles 4 nodes per iter
    int base = blockIdx.x * 160;
    for (int it = 0; it < 10; ++it) {
        int nb = base + it * 16;
        __syncthreads();
        for (int i = threadIdx.x; i < 1024; i += 256)
            sX[i >> 6][i & 63] = X[(nb + (i >> 6)) * 64 + (i & 63)];
        __syncthreads();
        float a0[4] = {0,0,0,0}, a1[4] = {0,0,0,0};
        #pragma unroll
        for (int k = 0; k < 64; ++k) {
            float w0 = sW0[k*64+f], w1 = sW1[k*64+f];
            #pragma unroll
            for (int m = 0; m < 4; ++m) {
                float xv = sX[q*4+m][k];
                a0[m] += xv * w0;
                a1[m] += xv * w1;
            }
        }
        #pragma unroll
        for (int m = 0; m < 4; ++m) {
            int n = nb + q*4 + m;
            g_y0[n*64+f] = a0[m];
            g_y1[n*64+f] = a1[m];
        }
    }
}

// ---------------- root transform: yr = X@root ----------------
__global__ __launch_bounds__(256) void k_mmr(int xsel, const float* __restrict__ Wr) {
    __shared__ float sW[4096];
    __shared__ float sX[16][64];
    const float* X = xsel ? g_hB : g_hA;
    for (int i = threadIdx.x; i < 4096; i += 256) sW[i] = Wr[i];
    int f = threadIdx.x & 63;
    int q = threadIdx.x >> 6;
    int base = blockIdx.x * 160;
    for (int it = 0; it < 10; ++it) {
        int nb = base + it * 16;
        __syncthreads();
        for (int i = threadIdx.x; i < 1024; i += 256)
            sX[i >> 6][i & 63] = X[(nb + (i >> 6)) * 64 + (i & 63)];
        __syncthreads();
        float ar[4] = {0,0,0,0};
        #pragma unroll
        for (int k = 0; k < 64; ++k) {
            float w = sW[k*64+f];
            #pragma unroll
            for (int m = 0; m < 4; ++m)
                ar[m] += sX[q*4+m][k] * w;
        }
        #pragma unroll
        for (int m = 0; m < 4; ++m)
            g_yr[(nb + q*4 + m)*64 + f] = ar[m];
    }
}

// ---------------- edge scatter: agg[dst] += y0[src]*(1-u) + y1[src]*u ----
__global__ void k_edge(const int* __restrict__ src, const int* __restrict__ dst,
                       const float* __restrict__ u) {
    int t = blockIdx.x * blockDim.x + threadIdx.x;   // exactly NE*16 threads
    int e = t >> 4;
    int j = t & 15;
    float uu = __ldg(&u[e]);
    int s = __ldg(&src[e]);
    int d = __ldg(&dst[e]);
    float4 a = ((const float4*)(g_y0 + (long)s * 64))[j];
    float4 b = ((const float4*)(g_y1 + (long)s * 64))[j];
    float w0 = 1.0f - uu;
    float4 m;
    m.x = a.x*w0 + b.x*uu;
    m.y = a.y*w0 + b.y*uu;
    m.z = a.z*w0 + b.z*uu;
    m.w = a.w*w0 + b.w*uu;
    red_add_v4(g_agg + (long)d * 64 + j * 4, m);
}

// ---------------- finalize: h = elu(agg/max(deg,1) + yr + b) ----------------
__global__ void k_finalize(const float* __restrict__ bias, int hsel) {
    int t = blockIdx.x * blockDim.x + threadIdx.x;   // exactly NN*16 threads
    int n = t >> 4, j = t & 15;
    float* hout = hsel ? g_hB : g_hA;
    float d = g_deg[n];
    float inv = 1.0f / (d < 1.0f ? 1.0f : d);
    float4 a = ((const float4*)g_agg)[t];
    float4 r = ((const float4*)g_yr)[t];
    float4 b = ((const float4*)bias)[j];
    float4 o;
    o.x = elu1(a.x*inv + r.x + b.x);
    o.y = elu1(a.y*inv + r.y + b.y);
    o.z = elu1(a.z*inv + r.z + b.z);
    o.w = elu1(a.w*inv + r.w + b.w);
    ((float4*)hout)[t] = o;
}

// ---------------- pooling: run-length local accumulation over sorted batch --
#define POOL_CHUNK 64
#define POOL_NCHUNK ((NN + POOL_CHUNK - 1) / POOL_CHUNK)   // 1250
__global__ void k_pool(const int* __restrict__ batch) {
    int t = blockIdx.x * blockDim.x + threadIdx.x;
    int j = t & 15;
    int c = t >> 4;
    if (c >= POOL_NCHUNK) return;
    int n0 = c * POOL_CHUNK;
    int n1 = n0 + POOL_CHUNK; if (n1 > NN) n1 = NN;
    const float4* h4 = (const float4*)g_hB;
    float4 acc = make_float4(0.f, 0.f, 0.f, 0.f);
    int g = batch[n0];
    for (int n = n0; n < n1; ++n) {
        int gg = batch[n];
        if (gg != g) {
            red_add_v4(&g_pooled[g * 64 + j * 4], acc);
            acc = make_float4(0.f, 0.f, 0.f, 0.f);
            g = gg;
        }
        float4 v = h4[(long)n * 16 + j];
        acc.x += v.x; acc.y += v.y; acc.z += v.z; acc.w += v.w;
    }
    red_add_v4(&g_pooled[g * 64 + j * 4], acc);
}

// ---------------- head: mean, FC(64->6), log_softmax ----------------
__global__ void k_head(const int* __restrict__ batch, const float* __restrict__ fcw,
                       const float* __restrict__ fcb, float* __restrict__ out) {
    int g = blockIdx.x * blockDim.x + threadIdx.x;
    if (g >= NG) return;
    int lo, hi, c0, c1;
    lo = 0; hi = NN;
    while (lo < hi) { int mid = (lo + hi) >> 1; if (batch[mid] < g) lo = mid + 1; else hi = mid; }
    c0 = lo;
    lo = 0; hi = NN;
    while (lo < hi) { int mid = (lo + hi) >> 1; if (batch[mid] < g + 1) lo = mid + 1; else hi = mid; }
    c1 = lo;
    float cnt = (float)(c1 - c0);
    float inv = 1.0f / (cnt < 1.0f ? 1.0f : cnt);

    float logit[6];
    #pragma unroll
    for (int cc = 0; cc < 6; ++cc) logit[cc] = fcb[cc];
    for (int k = 0; k < 64; ++k) {
        float p = g_pooled[g * 64 + k] * inv;
        #pragma unroll
        for (int cc = 0; cc < 6; ++cc) logit[cc] += p * fcw[k * 6 + cc];
    }
    float m = logit[0];
    #pragma unroll
    for (int cc = 1; cc < 6; ++cc) m = fmaxf(m, logit[cc]);
    float s = 0.f;
    #pragma unroll
    for (int cc = 0; cc < 6; ++cc) s += expf(logit[cc] - m);
    float l = logf(s);
    #pragma unroll
    for (int cc = 0; cc < 6; ++cc) out[g * 6 + cc] = logit[cc] - m - l;
}

// ---------------- launch ----------------
extern "C" void kernel_launch(void* const* d_in, const int* in_sizes, int n_in,
                              void* d_out, int out_size) {
    const float* x      = (const float*)d_in[0];
    const float* pseudo = (const float*)d_in[1];
    const int*   ei     = (const int*)d_in[2];
    const int*   batch  = (const int*)d_in[3];
    const float* W1 = (const float*)d_in[4];
    const float* r1 = (const float*)d_in[5];
    const float* b1 = (const float*)d_in[6];
    const float* W2 = (const float*)d_in[7];
    const float* r2 = (const float*)d_in[8];
    const float* b2 = (const float*)d_in[9];
    const float* W3 = (const float*)d_in[10];
    const float* r3 = (const float*)d_in[11];
    const float* b3 = (const float*)d_in[12];
    const float* W4 = (const float*)d_in[13];
    const float* r4 = (const float*)d_in[14];
    const float* b4 = (const float*)d_in[15];
    const float* fcw = (const float*)d_in[16];
    const float* fcb = (const float*)d_in[17];
    float* out = (float*)d_out;

    const int* src = ei;
    const int* dst = ei + NE;

    k_zero_misc<<<(NN + NG*FF + 255)/256, 256>>>();
    k_deg<<<NE/256, 256>>>(dst);

    // ---- layer 1 (Fin=3 -> 64) ----
    k_l1<<<(NN*FF)/256, 256>>>(x, W1, r1);
    k_zero_agg<<<(NN*FF)/256, 256>>>();
    k_edge<<<(NE*16)/256, 256>>>(src, dst, pseudo);
    k_finalize<<<(NN*16)/256, 256>>>(b1, 0);          // -> hA

    // ---- layer 2 ----
    k_mm2<<<NN/160, 256>>>(0, W2, W2 + 4096);
    k_mmr<<<NN/160, 256>>>(0, r2);
    k_zero_agg<<<(NN*FF)/256, 256>>>();
    k_edge<<<(NE*16)/256, 256>>>(src, dst, pseudo);
    k_finalize<<<(NN*16)/256, 256>>>(b2, 1);          // -> hB

    // ---- layer 3 ----
    k_mm2<<<NN/160, 256>>>(1, W3, W3 + 4096);
    k_mmr<<<NN/160, 256>>>(1, r3);
    k_zero_agg<<<(NN*FF)/256, 256>>>();
    k_edge<<<(NE*16)/256, 256>>>(src, dst, pseudo);
    k_finalize<<<(NN*16)/256, 256>>>(b3, 0);          // -> hA

    // ---- layer 4 ----
    k_mm2<<<NN/160, 256>>>(0, W4, W4 + 4096);
    k_mmr<<<NN/160, 256>>>(0, r4);
    k_zero_agg<<<(NN*FF)/256, 256>>>();
    k_edge<<<(NE*16)/256, 256>>>(src, dst, pseudo);
    k_finalize<<<(NN*16)/256, 256>>>(b4, 1);          // -> hB

    // ---- pooling + head ----
    k_pool<<<(POOL_NCHUNK*16 + 255)/256, 256>>>(batch);
    k_head<<<(NG + 255)/256, 256>>>(batch, fcw, fcb, out);
}

// round 4
// speedup vs baseline: 1.3960x; 1.3960x over previous
#include <cuda_runtime.h>
#include <math.h>

#define NN 80000
#define NE 1280000
#define NG 512
#define FF 64

// ---------------- scratch (device globals, no allocation) ----------------
__device__ __align__(16) float g_A0[NN*FF];
__device__ __align__(16) float g_A1[NN*FF];
__device__ __align__(16) float g_hA[NN*FF];
__device__ __align__(16) float g_hB[NN*FF];
__device__ __align__(16) float g_B0[NN*4];   // layer-1 3-dim accumulators (padded)
__device__ __align__(16) float g_B1[NN*4];
__device__ __align__(16) float g_pooled[NG*FF];
__device__ int   g_cnt[NN];
__device__ int   g_cursor[NN];
__device__ int   g_off[NN+1];
__device__ int   g_esrc[NE];
__device__ float g_eu[NE];

// ---------------- helpers ----------------
__device__ __forceinline__ void red_add_v4(float* p, float4 v) {
    asm volatile("red.global.add.v4.f32 [%0], {%1,%2,%3,%4};"
                 :: "l"(p), "f"(v.x), "f"(v.y), "f"(v.z), "f"(v.w) : "memory");
}
__device__ __forceinline__ float elu1(float v) { return v > 0.0f ? v : expm1f(v); }

// ---------------- CSR build ----------------
__global__ void k_zero() {
    int t = blockIdx.x * blockDim.x + threadIdx.x;
    if (t < NN) { g_cnt[t] = 0; g_cursor[t] = 0; }
    if (t < NG*FF) g_pooled[t] = 0.0f;
}

__global__ void k_hist(const int* __restrict__ dst) {
    int e = blockIdx.x * blockDim.x + threadIdx.x;   // exactly NE threads
    atomicAdd(&g_cnt[dst[e]], 1);
}

__global__ void k_scan() {   // single block, 1024 threads
    __shared__ int warp_excl[32];
    __shared__ int s_total;
    __shared__ int s_carry;
    int tid = threadIdx.x, lane = tid & 31, wid = tid >> 5;
    if (tid == 0) s_carry = 0;
    __syncthreads();
    for (int base = 0; base < NN; base += 1024) {
        int i = base + tid;
        int v = (i < NN) ? g_cnt[i] : 0;
        int inc = v;
        #pragma unroll
        for (int o = 1; o < 32; o <<= 1) {
            int nv = __shfl_up_sync(0xffffffffu, inc, o);
            if (lane >= o) inc += nv;
        }
        if (lane == 31) warp_excl[wid] = inc;
        __syncthreads();
        if (wid == 0) {
            int wv = warp_excl[lane];
            int winc = wv;
            #pragma unroll
            for (int o = 1; o < 32; o <<= 1) {
                int nv = __shfl_up_sync(0xffffffffu, winc, o);
                if (lane >= o) winc += nv;
            }
            warp_excl[lane] = winc - wv;
            if (lane == 31) s_total = winc;
        }
        __syncthreads();
        if (i < NN) g_off[i] = s_carry + warp_excl[wid] + (inc - v);
        __syncthreads();
        if (tid == 0) s_carry += s_total;
        __syncthreads();
    }
    if (tid == 0) g_off[NN] = NE;
}

__global__ void k_fill(const int* __restrict__ src, const int* __restrict__ dst,
                       const float* __restrict__ u) {
    int e = blockIdx.x * blockDim.x + threadIdx.x;   // exactly NE threads
    int d = dst[e];
    int pos = g_off[d] + atomicAdd(&g_cursor[d], 1);
    g_esrc[pos] = src[e];
    g_eu[pos]   = u[e];
}

// ---------------- layer 1: aggregate raw x (3-dim) then transform ----------
__global__ void k_gather3(const float* __restrict__ x) {
    int n = blockIdx.x * blockDim.x + threadIdx.x;
    if (n >= NN) return;
    int beg = g_off[n], end = g_off[n+1];
    float a00=0,a01=0,a02=0, a10=0,a11=0,a12=0;
    for (int e = beg; e < end; ++e) {
        int s = g_esrc[e];
        float uu = g_eu[e];
        float w0 = 1.0f - uu;
        float x0 = __ldg(&x[s*3+0]);
        float x1 = __ldg(&x[s*3+1]);
        float x2 = __ldg(&x[s*3+2]);
        a00 += w0*x0; a01 += w0*x1; a02 += w0*x2;
        a10 += uu*x0; a11 += uu*x1; a12 += uu*x2;
    }
    g_B0[n*4+0]=a00; g_B0[n*4+1]=a01; g_B0[n*4+2]=a02;
    g_B1[n*4+0]=a10; g_B1[n*4+1]=a11; g_B1[n*4+2]=a12;
}

__global__ void k_layer1(const float* __restrict__ x, const float* __restrict__ W,
                         const float* __restrict__ root, const float* __restrict__ b) {
    int t = blockIdx.x * blockDim.x + threadIdx.x;   // exactly NN*64 threads
    int n = t >> 6, f = t & 63;
    float agg = g_B0[n*4+0]*__ldg(&W[f])      + g_B0[n*4+1]*__ldg(&W[64+f])  + g_B0[n*4+2]*__ldg(&W[128+f])
              + g_B1[n*4+0]*__ldg(&W[192+f])  + g_B1[n*4+1]*__ldg(&W[256+f]) + g_B1[n*4+2]*__ldg(&W[320+f]);
    int dg = g_off[n+1] - g_off[n];
    float inv = 1.0f / (dg < 1 ? 1 : dg);
    float yr = x[n*3+0]*__ldg(&root[f]) + x[n*3+1]*__ldg(&root[64+f]) + x[n*3+2]*__ldg(&root[128+f]);
    g_hA[t] = elu1(agg*inv + yr + __ldg(&b[f]));
}

// ---------------- edge gather (layers 2-4): A0/A1 = weighted sums of h[src] --
__global__ void k_gather(int insel) {
    int t = blockIdx.x * blockDim.x + threadIdx.x;   // exactly NN*16 threads
    int n = t >> 4, j = t & 15;
    const float4* H = (const float4*)(insel ? g_hB : g_hA);
    int beg = g_off[n], end = g_off[n+1];
    float4 s0 = make_float4(0.f,0.f,0.f,0.f);
    float4 s1 = make_float4(0.f,0.f,0.f,0.f);
    for (int e = beg; e < end; ++e) {
        int s = g_esrc[e];
        float uu = g_eu[e];
        float w0 = 1.0f - uu;
        float4 v = H[(long)s * 16 + j];
        s0.x += w0*v.x; s0.y += w0*v.y; s0.z += w0*v.z; s0.w += w0*v.w;
        s1.x += uu*v.x; s1.y += uu*v.y; s1.z += uu*v.z; s1.w += uu*v.w;
    }
    ((float4*)g_A0)[t] = s0;
    ((float4*)g_A1)[t] = s1;
}

// ---------------- fused layer: h_out = elu((A0@W0+A1@W1)/deg + h_in@root + b)
// block = 128 threads, 32 nodes per block. Register tile 4 nodes x 4 cols.
__global__ __launch_bounds__(128) void k_layer(int insel, int outsel,
                                               const float* __restrict__ W,
                                               const float* __restrict__ root,
                                               const float* __restrict__ bias) {
    __shared__ float sA0[32*64];
    __shared__ float sA1[32*64];
    __shared__ float sH [32*64];
    const float* hin  = insel  ? g_hB : g_hA;
    float*       hout = outsel ? g_hB : g_hA;
    int nb = blockIdx.x * 32;

    {
        const float4* a0 = (const float4*)(g_A0 + (long)nb*64);
        const float4* a1 = (const float4*)(g_A1 + (long)nb*64);
        const float4* hh = (const float4*)(hin  + (long)nb*64);
        float4* d0 = (float4*)sA0; float4* d1 = (float4*)sA1; float4* dh = (float4*)sH;
        for (int i = threadIdx.x; i < 512; i += 128) {
            d0[i] = a0[i]; d1[i] = a1[i]; dh[i] = hh[i];
        }
    }
    __syncthreads();

    int f4 = threadIdx.x & 15;   // output col group (4 cols)
    int mg = threadIdx.x >> 4;   // node group (4 nodes), 0..7

    float acc[4][4];  float accr[4][4];
    #pragma unroll
    for (int i = 0; i < 4; ++i)
        #pragma unroll
        for (int jj = 0; jj < 4; ++jj) { acc[i][jj] = 0.f; accr[i][jj] = 0.f; }

    const float4* W0 = (const float4*)W;            // (64,64) row-major, 16 float4/row
    const float4* W1 = (const float4*)(W + 4096);
    const float4* Wr = (const float4*)root;

    for (int k = 0; k < 64; ++k) {
        float4 w0 = __ldg(&W0[k*16 + f4]);
        float4 w1 = __ldg(&W1[k*16 + f4]);
        float4 wr = __ldg(&Wr[k*16 + f4]);
        #pragma unroll
        for (int i = 0; i < 4; ++i) {
            int r = mg*4 + i;
            float xa = sA0[r*64 + k];
            float xb = sA1[r*64 + k];
            float xh = sH [r*64 + k];
            acc[i][0] += xa*w0.x + xb*w1.x;
            acc[i][1] += xa*w0.y + xb*w1.y;
            acc[i][2] += xa*w0.z + xb*w1.z;
            acc[i][3] += xa*w0.w + xb*w1.w;
            accr[i][0] += xh*wr.x;
            accr[i][1] += xh*wr.y;
            accr[i][2] += xh*wr.z;
            accr[i][3] += xh*wr.w;
        }
    }

    float4 bv = __ldg(&((const float4*)bias)[f4]);
    #pragma unroll
    for (int i = 0; i < 4; ++i) {
        int n = nb + mg*4 + i;
        int dg = g_off[n+1] - g_off[n];
        float inv = 1.0f / (dg < 1 ? 1 : dg);
        float4 o;
        o.x = elu1(acc[i][0]*inv + accr[i][0] + bv.x);
        o.y = elu1(acc[i][1]*inv + accr[i][1] + bv.y);
        o.z = elu1(acc[i][2]*inv + accr[i][2] + bv.z);
        o.w = elu1(acc[i][3]*inv + accr[i][3] + bv.w);
        ((float4*)(hout + (long)n*64))[f4] = o;
    }
}

// ---------------- pooling: run-length local accumulation over sorted batch --
#define POOL_CHUNK 64
#define POOL_NCHUNK ((NN + POOL_CHUNK - 1) / POOL_CHUNK)   // 1250
__global__ void k_pool(const int* __restrict__ batch) {
    int t = blockIdx.x * blockDim.x + threadIdx.x;
    int j = t & 15;
    int c = t >> 4;
    if (c >= POOL_NCHUNK) return;
    int n0 = c * POOL_CHUNK;
    int n1 = n0 + POOL_CHUNK; if (n1 > NN) n1 = NN;
    const float4* h4 = (const float4*)g_hB;
    float4 acc = make_float4(0.f,0.f,0.f,0.f);
    int g = batch[n0];
    for (int n = n0; n < n1; ++n) {
        int gg = batch[n];
        if (gg != g) {
            red_add_v4(&g_pooled[g*64 + j*4], acc);
            acc = make_float4(0.f,0.f,0.f,0.f);
            g = gg;
        }
        float4 v = h4[(long)n*16 + j];
        acc.x += v.x; acc.y += v.y; acc.z += v.z; acc.w += v.w;
    }
    red_add_v4(&g_pooled[g*64 + j*4], acc);
}

// ---------------- head: mean, FC(64->6), log_softmax ----------------
__global__ void k_head(const int* __restrict__ batch, const float* __restrict__ fcw,
                       const float* __restrict__ fcb, float* __restrict__ out) {
    int g = blockIdx.x * blockDim.x + threadIdx.x;
    if (g >= NG) return;
    int lo, hi, c0, c1;
    lo = 0; hi = NN;
    while (lo < hi) { int mid = (lo + hi) >> 1; if (batch[mid] < g) lo = mid + 1; else hi = mid; }
    c0 = lo;
    lo = 0; hi = NN;
    while (lo < hi) { int mid = (lo + hi) >> 1; if (batch[mid] < g + 1) lo = mid + 1; else hi = mid; }
    c1 = lo;
    float cnt = (float)(c1 - c0);
    float inv = 1.0f / (cnt < 1.0f ? 1.0f : cnt);

    float logit[6];
    #pragma unroll
    for (int cc = 0; cc < 6; ++cc) logit[cc] = fcb[cc];
    for (int k = 0; k < 64; ++k) {
        float p = g_pooled[g*64 + k] * inv;
        #pragma unroll
        for (int cc = 0; cc < 6; ++cc) logit[cc] += p * fcw[k*6 + cc];
    }
    float m = logit[0];
    #pragma unroll
    for (int cc = 1; cc < 6; ++cc) m = fmaxf(m, logit[cc]);
    float s = 0.f;
    #pragma unroll
    for (int cc = 0; cc < 6; ++cc) s += expf(logit[cc] - m);
    float l = logf(s);
    #pragma unroll
    for (int cc = 0; cc < 6; ++cc) out[g*6 + cc] = logit[cc] - m - l;
}

// ---------------- launch ----------------
extern "C" void kernel_launch(void* const* d_in, const int* in_sizes, int n_in,
                              void* d_out, int out_size) {
    const float* x      = (const float*)d_in[0];
    const float* pseudo = (const float*)d_in[1];
    const int*   ei     = (const int*)d_in[2];
    const int*   batch  = (const int*)d_in[3];
    const float* W1 = (const float*)d_in[4];
    const float* r1 = (const float*)d_in[5];
    const float* b1 = (const float*)d_in[6];
    const float* W2 = (const float*)d_in[7];
    const float* r2 = (const float*)d_in[8];
    const float* b2 = (const float*)d_in[9];
    const float* W3 = (const float*)d_in[10];
    const float* r3 = (const float*)d_in[11];
    const float* b3 = (const float*)d_in[12];
    const float* W4 = (const float*)d_in[13];
    const float* r4 = (const float*)d_in[14];
    const float* b4 = (const float*)d_in[15];
    const float* fcw = (const float*)d_in[16];
    const float* fcb = (const float*)d_in[17];
    float* out = (float*)d_out;

    const int* src = ei;
    const int* dst = ei + NE;

    // CSR build (reused by all 4 layers; deg comes from g_off)
    k_zero<<<(NN + 255)/256, 256>>>();
    k_hist<<<NE/256, 256>>>(dst);
    k_scan<<<1, 1024>>>();
    k_fill<<<NE/256, 256>>>(src, dst, pseudo);

    // layer 1 (Fin=3)
    k_gather3<<<(NN + 255)/256, 256>>>(x);
    k_layer1<<<(NN*FF)/256, 256>>>(x, W1, r1, b1);           // -> hA

    // layer 2
    k_gather<<<(NN*16)/256, 256>>>(0);
    k_layer<<<NN/32, 128>>>(0, 1, W2, r2, b2);               // hA -> hB
    // layer 3
    k_gather<<<(NN*16)/256, 256>>>(1);
    k_layer<<<NN/32, 128>>>(1, 0, W3, r3, b3);               // hB -> hA
    // layer 4
    k_gather<<<(NN*16)/256, 256>>>(0);
    k_layer<<<NN/32, 128>>>(0, 1, W4, r4, b4);               // hA -> hB

    // pooling + head
    k_pool<<<(POOL_NCHUNK*16 + 255)/256, 256>>>(batch);
    k_head<<<(NG + 255)/256, 256>>>(batch, fcw, fcb, out);
}

// round 5
// speedup vs baseline: 1.6862x; 1.2079x over previous
#include <cuda_runtime.h>
#include <math.h>

#define NN 80000
#define NE 1280000
#define NG 512
#define FF 64

// ---------------- scratch (device globals, no allocation) ----------------
__device__ __align__(16) float g_hA[NN*FF];
__device__ __align__(16) float g_hB[NN*FF];
__device__ __align__(16) float g_B0[NN*4];   // layer-1 3-dim accumulators (padded)
__device__ __align__(16) float g_B1[NN*4];
__device__ __align__(16) float g_pooled[NG*FF];
__device__ int   g_cnt[NN];
__device__ int   g_cursor[NN];
__device__ int   g_off[NN+1];
__device__ int   g_esrc[NE];
__device__ float g_eu[NE];

// ---------------- helpers ----------------
__device__ __forceinline__ void red_add_v4(float* p, float4 v) {
    asm volatile("red.global.add.v4.f32 [%0], {%1,%2,%3,%4};"
                 :: "l"(p), "f"(v.x), "f"(v.y), "f"(v.z), "f"(v.w) : "memory");
}
__device__ __forceinline__ float elu1(float v) { return v > 0.0f ? v : expm1f(v); }

// ---------------- CSR build ----------------
__global__ void k_zero() {
    int t = blockIdx.x * blockDim.x + threadIdx.x;
    if (t < NN) { g_cnt[t] = 0; g_cursor[t] = 0; }
    if (t < NG*FF) g_pooled[t] = 0.0f;
}

__global__ void k_hist(const int* __restrict__ dst) {
    int e = blockIdx.x * blockDim.x + threadIdx.x;   // exactly NE threads
    atomicAdd(&g_cnt[dst[e]], 1);
}

__global__ void k_scan() {   // single block, 1024 threads
    __shared__ int warp_excl[32];
    __shared__ int s_total;
    __shared__ int s_carry;
    int tid = threadIdx.x, lane = tid & 31, wid = tid >> 5;
    if (tid == 0) s_carry = 0;
    __syncthreads();
    for (int base = 0; base < NN; base += 1024) {
        int i = base + tid;
        int v = (i < NN) ? g_cnt[i] : 0;
        int inc = v;
        #pragma unroll
        for (int o = 1; o < 32; o <<= 1) {
            int nv = __shfl_up_sync(0xffffffffu, inc, o);
            if (lane >= o) inc += nv;
        }
        if (lane == 31) warp_excl[wid] = inc;
        __syncthreads();
        if (wid == 0) {
            int wv = warp_excl[lane];
            int winc = wv;
            #pragma unroll
            for (int o = 1; o < 32; o <<= 1) {
                int nv = __shfl_up_sync(0xffffffffu, winc, o);
                if (lane >= o) winc += nv;
            }
            warp_excl[lane] = winc - wv;
            if (lane == 31) s_total = winc;
        }
        __syncthreads();
        if (i < NN) g_off[i] = s_carry + warp_excl[wid] + (inc - v);
        __syncthreads();
        if (tid == 0) s_carry += s_total;
        __syncthreads();
    }
    if (tid == 0) g_off[NN] = NE;
}

__global__ void k_fill(const int* __restrict__ src, const int* __restrict__ dst,
                       const float* __restrict__ u) {
    int e = blockIdx.x * blockDim.x + threadIdx.x;   // exactly NE threads
    int d = dst[e];
    int pos = g_off[d] + atomicAdd(&g_cursor[d], 1);
    g_esrc[pos] = src[e];
    g_eu[pos]   = u[e];
}

// ---------------- layer 1: aggregate raw x (3-dim) then transform ----------
__global__ void k_gather3(const float* __restrict__ x) {
    int n = blockIdx.x * blockDim.x + threadIdx.x;
    if (n >= NN) return;
    int beg = g_off[n], end = g_off[n+1];
    float a00=0,a01=0,a02=0, a10=0,a11=0,a12=0;
    for (int e = beg; e < end; ++e) {
        int s = g_esrc[e];
        float uu = g_eu[e];
        float w0 = 1.0f - uu;
        float x0 = __ldg(&x[s*3+0]);
        float x1 = __ldg(&x[s*3+1]);
        float x2 = __ldg(&x[s*3+2]);
        a00 += w0*x0; a01 += w0*x1; a02 += w0*x2;
        a10 += uu*x0; a11 += uu*x1; a12 += uu*x2;
    }
    g_B0[n*4+0]=a00; g_B0[n*4+1]=a01; g_B0[n*4+2]=a02;
    g_B1[n*4+0]=a10; g_B1[n*4+1]=a11; g_B1[n*4+2]=a12;
}

__global__ void k_layer1(const float* __restrict__ x, const float* __restrict__ W,
                         const float* __restrict__ root, const float* __restrict__ b) {
    int t = blockIdx.x * blockDim.x + threadIdx.x;   // exactly NN*64 threads
    int n = t >> 6, f = t & 63;
    float agg = g_B0[n*4+0]*__ldg(&W[f])      + g_B0[n*4+1]*__ldg(&W[64+f])  + g_B0[n*4+2]*__ldg(&W[128+f])
              + g_B1[n*4+0]*__ldg(&W[192+f])  + g_B1[n*4+1]*__ldg(&W[256+f]) + g_B1[n*4+2]*__ldg(&W[320+f]);
    int dg = g_off[n+1] - g_off[n];
    float inv = 1.0f / (dg < 1 ? 1 : dg);
    float yr = x[n*3+0]*__ldg(&root[f]) + x[n*3+1]*__ldg(&root[64+f]) + x[n*3+2]*__ldg(&root[128+f]);
    g_hA[t] = elu1(agg*inv + yr + __ldg(&b[f]));
}

// ---------------- fused gather + GEMM layer (layers 2-4) -------------------
// h_out = elu( [A0*inv | A1*inv | H] @ [W0; W1; root] + b )
// block = 256 threads (8 warps), 64 nodes. smem tile 64 x 192 floats (48KB).
__global__ __launch_bounds__(256) void k_glayer(int insel, int outsel,
                                                const float* __restrict__ W,
                                                const float* __restrict__ root,
                                                const float* __restrict__ bias) {
    __shared__ float sF[64 * 192];                  // [node][A0(64)|A1(64)|H(64)]
    const float* hin  = insel  ? g_hB : g_hA;
    float*       hout = outsel ? g_hB : g_hA;
    const int nb = blockIdx.x * 64;
    const int tid = threadIdx.x;
    const int lane = tid & 31;
    const int warp = tid >> 5;                      // 0..7
    const int j = lane & 15;                        // float4 index within 64-float row
    const int half = lane >> 4;                     // edge-range half

    float4* sF4 = (float4*)sF;                      // 48 float4 per node row
    const float4* H4 = (const float4*)hin;

    // stage H rows into sF[.][128..191]
    for (int i = tid; i < 64*16; i += 256) {
        int r = i >> 4, jj = i & 15;
        sF4[r*48 + 32 + jj] = H4[(long)(nb + r)*16 + jj];
    }

    // gather: 1 warp per node, 8 nodes per warp
    for (int q = 0; q < 8; ++q) {
        int n = nb + warp*8 + q;
        int beg = g_off[n], end = g_off[n+1];
        int d = end - beg;
        float inv = 1.0f / (d < 1 ? 1 : d);
        int mid = beg + ((d + 1) >> 1);
        int e0 = half ? mid : beg;
        int e1 = half ? end : mid;
        float4 s0 = make_float4(0.f,0.f,0.f,0.f);
        float4 s1 = make_float4(0.f,0.f,0.f,0.f);
        for (int e = e0; e < e1; ++e) {
            int s = __ldg(&g_esrc[e]);
            float uu = __ldg(&g_eu[e]);
            float w0 = 1.0f - uu;
            float4 v = H4[(long)s*16 + j];
            s0.x += w0*v.x; s0.y += w0*v.y; s0.z += w0*v.z; s0.w += w0*v.w;
            s1.x += uu*v.x; s1.y += uu*v.y; s1.z += uu*v.z; s1.w += uu*v.w;
        }
        // combine halves
        s0.x += __shfl_xor_sync(0xffffffffu, s0.x, 16);
        s0.y += __shfl_xor_sync(0xffffffffu, s0.y, 16);
        s0.z += __shfl_xor_sync(0xffffffffu, s0.z, 16);
        s0.w += __shfl_xor_sync(0xffffffffu, s0.w, 16);
        s1.x += __shfl_xor_sync(0xffffffffu, s1.x, 16);
        s1.y += __shfl_xor_sync(0xffffffffu, s1.y, 16);
        s1.z += __shfl_xor_sync(0xffffffffu, s1.z, 16);
        s1.w += __shfl_xor_sync(0xffffffffu, s1.w, 16);
        int r = warp*8 + q;
        if (half == 0) {
            s0.x *= inv; s0.y *= inv; s0.z *= inv; s0.w *= inv;
            sF4[r*48 + j] = s0;
        } else {
            s1.x *= inv; s1.y *= inv; s1.z *= inv; s1.w *= inv;
            sF4[r*48 + 16 + j] = s1;
        }
    }
    __syncthreads();

    // GEMM: thread tile = 4 nodes x 4 cols, k-chunks of 4 via float4
    const int f4 = tid & 15;                        // output col group
    const int mg = tid >> 4;                        // node group 0..15

    float acc[4][4];
    #pragma unroll
    for (int i = 0; i < 4; ++i)
        #pragma unroll
        for (int c = 0; c < 4; ++c) acc[i][c] = 0.f;

    const float4* W4 = (const float4*)W;            // 128 rows (W0;W1), 16 float4/row
    const float4* R4 = (const float4*)root;         // 64 rows

    #pragma unroll 4
    for (int kc = 0; kc < 32; ++kc) {               // W0;W1 part, k = 4*kc
        float4 w0 = __ldg(&W4[(4*kc+0)*16 + f4]);
        float4 w1 = __ldg(&W4[(4*kc+1)*16 + f4]);
        float4 w2 = __ldg(&W4[(4*kc+2)*16 + f4]);
        float4 w3 = __ldg(&W4[(4*kc+3)*16 + f4]);
        #pragma unroll
        for (int i = 0; i < 4; ++i) {
            int r = mg*4 + i;
            float4 xv = sF4[r*48 + kc];
            acc[i][0] += xv.x*w0.x + xv.y*w1.x + xv.z*w2.x + xv.w*w3.x;
            acc[i][1] += xv.x*w0.y + xv.y*w1.y + xv.z*w2.y + xv.w*w3.y;
            acc[i][2] += xv.x*w0.z + xv.y*w1.z + xv.z*w2.z + xv.w*w3.z;
            acc[i][3] += xv.x*w0.w + xv.y*w1.w + xv.z*w2.w + xv.w*w3.w;
        }
    }
    #pragma unroll 4
    for (int kc = 0; kc < 16; ++kc) {               // root part
        float4 w0 = __ldg(&R4[(4*kc+0)*16 + f4]);
        float4 w1 = __ldg(&R4[(4*kc+1)*16 + f4]);
        float4 w2 = __ldg(&R4[(4*kc+2)*16 + f4]);
        float4 w3 = __ldg(&R4[(4*kc+3)*16 + f4]);
        #pragma unroll
        for (int i = 0; i < 4; ++i) {
            int r = mg*4 + i;
            float4 xv = sF4[r*48 + 32 + kc];
            acc[i][0] += xv.x*w0.x + xv.y*w1.x + xv.z*w2.x + xv.w*w3.x;
            acc[i][1] += xv.x*w0.y + xv.y*w1.y + xv.z*w2.y + xv.w*w3.y;
            acc[i][2] += xv.x*w0.z + xv.y*w1.z + xv.z*w2.z + xv.w*w3.z;
            acc[i][3] += xv.x*w0.w + xv.y*w1.w + xv.z*w2.w + xv.w*w3.w;
        }
    }

    float4 bv = __ldg(&((const float4*)bias)[f4]);
    #pragma unroll
    for (int i = 0; i < 4; ++i) {
        int n = nb + mg*4 + i;
        float4 o;
        o.x = elu1(acc[i][0] + bv.x);
        o.y = elu1(acc[i][1] + bv.y);
        o.z = elu1(acc[i][2] + bv.z);
        o.w = elu1(acc[i][3] + bv.w);
        ((float4*)(hout + (long)n*64))[f4] = o;
    }
}

// ---------------- pooling: run-length local accumulation over sorted batch --
#define POOL_CHUNK 64
#define POOL_NCHUNK ((NN + POOL_CHUNK - 1) / POOL_CHUNK)   // 1250
__global__ void k_pool(const int* __restrict__ batch) {
    int t = blockIdx.x * blockDim.x + threadIdx.x;
    int j = t & 15;
    int c = t >> 4;
    if (c >= POOL_NCHUNK) return;
    int n0 = c * POOL_CHUNK;
    int n1 = n0 + POOL_CHUNK; if (n1 > NN) n1 = NN;
    const float4* h4 = (const float4*)g_hB;
    float4 acc = make_float4(0.f,0.f,0.f,0.f);
    int g = batch[n0];
    for (int n = n0; n < n1; ++n) {
        int gg = batch[n];
        if (gg != g) {
            red_add_v4(&g_pooled[g*64 + j*4], acc);
            acc = make_float4(0.f,0.f,0.f,0.f);
            g = gg;
        }
        float4 v = h4[(long)n*16 + j];
        acc.x += v.x; acc.y += v.y; acc.z += v.z; acc.w += v.w;
    }
    red_add_v4(&g_pooled[g*64 + j*4], acc);
}

// ---------------- head: mean, FC(64->6), log_softmax ----------------
__global__ void k_head(const int* __restrict__ batch, const float* __restrict__ fcw,
                       const float* __restrict__ fcb, float* __restrict__ out) {
    int g = blockIdx.x * blockDim.x + threadIdx.x;
    if (g >= NG) return;
    int lo, hi, c0, c1;
    lo = 0; hi = NN;
    while (lo < hi) { int mid = (lo + hi) >> 1; if (batch[mid] < g) lo = mid + 1; else hi = mid; }
    c0 = lo;
    lo = 0; hi = NN;
    while (lo < hi) { int mid = (lo + hi) >> 1; if (batch[mid] < g + 1) lo = mid + 1; else hi = mid; }
    c1 = lo;
    float cnt = (float)(c1 - c0);
    float inv = 1.0f / (cnt < 1.0f ? 1.0f : cnt);

    float logit[6];
    #pragma unroll
    for (int cc = 0; cc < 6; ++cc) logit[cc] = fcb[cc];
    for (int k = 0; k < 64; ++k) {
        float p = g_pooled[g*64 + k] * inv;
        #pragma unroll
        for (int cc = 0; cc < 6; ++cc) logit[cc] += p * fcw[k*6 + cc];
    }
    float m = logit[0];
    #pragma unroll
    for (int cc = 1; cc < 6; ++cc) m = fmaxf(m, logit[cc]);
    float s = 0.f;
    #pragma unroll
    for (int cc = 0; cc < 6; ++cc) s += expf(logit[cc] - m);
    float l = logf(s);
    #pragma unroll
    for (int cc = 0; cc < 6; ++cc) out[g*6 + cc] = logit[cc] - m - l;
}

// ---------------- launch ----------------
extern "C" void kernel_launch(void* const* d_in, const int* in_sizes, int n_in,
                              void* d_out, int out_size) {
    const float* x      = (const float*)d_in[0];
    const float* pseudo = (const float*)d_in[1];
    const int*   ei     = (const int*)d_in[2];
    const int*   batch  = (const int*)d_in[3];
    const float* W1 = (const float*)d_in[4];
    const float* r1 = (const float*)d_in[5];
    const float* b1 = (const float*)d_in[6];
    const float* W2 = (const float*)d_in[7];
    const float* r2 = (const float*)d_in[8];
    const float* b2 = (const float*)d_in[9];
    const float* W3 = (const float*)d_in[10];
    const float* r3 = (const float*)d_in[11];
    const float* b3 = (const float*)d_in[12];
    const float* W4 = (const float*)d_in[13];
    const float* r4 = (const float*)d_in[14];
    const float* b4 = (const float*)d_in[15];
    const float* fcw = (const float*)d_in[16];
    const float* fcb = (const float*)d_in[17];
    float* out = (float*)d_out;

    const int* src = ei;
    const int* dst = ei + NE;

    // CSR build (reused by all 4 layers; deg comes from g_off)
    k_zero<<<(NN + 255)/256, 256>>>();
    k_hist<<<NE/256, 256>>>(dst);
    k_scan<<<1, 1024>>>();
    k_fill<<<NE/256, 256>>>(src, dst, pseudo);

    // layer 1 (Fin=3)
    k_gather3<<<(NN + 255)/256, 256>>>(x);
    k_layer1<<<(NN*FF)/256, 256>>>(x, W1, r1, b1);           // -> hA

    // layers 2-4: fused gather+GEMM
    k_glayer<<<NN/64, 256>>>(0, 1, W2, r2, b2);              // hA -> hB
    k_glayer<<<NN/64, 256>>>(1, 0, W3, r3, b3);              // hB -> hA
    k_glayer<<<NN/64, 256>>>(0, 1, W4, r4, b4);              // hA -> hB

    // pooling + head
    k_pool<<<(POOL_NCHUNK*16 + 255)/256, 256>>>(batch);
    k_head<<<(NG + 255)/256, 256>>>(batch, fcw, fcb, out);
}

// round 6
// speedup vs baseline: 1.8657x; 1.1065x over previous
#include <cuda_runtime.h>
#include <math.h>

#define NN 80000
#define NE 1280000
#define NG 512
#define FF 64

// ---------------- scratch (device globals, no allocation) ----------------
__device__ __align__(16) float g_hA[NN*FF];
__device__ __align__(16) float g_hB[NN*FF];
__device__ __align__(16) float g_B0[NN*4];
__device__ __align__(16) float g_B1[NN*4];
__device__ __align__(16) float g_pooled[NG*FF];
__device__ int   g_cnt[NN];
__device__ int   g_cursor[NN];
__device__ int   g_off[NN+1];
__device__ int   g_bsum[320];
__device__ int   g_boff[320];
__device__ int   g_esrc[NE];
__device__ float g_eu[NE];

// ---------------- helpers ----------------
__device__ __forceinline__ void red_add_v4(float* p, float4 v) {
    asm volatile("red.global.add.v4.f32 [%0], {%1,%2,%3,%4};"
                 :: "l"(p), "f"(v.x), "f"(v.y), "f"(v.z), "f"(v.w) : "memory");
}
__device__ __forceinline__ float elu1(float v) { return v > 0.0f ? v : expm1f(v); }

// ---------------- CSR build ----------------
__global__ void k_zero() {
    int t = blockIdx.x * blockDim.x + threadIdx.x;
    if (t < NN) { g_cnt[t] = 0; g_cursor[t] = 0; }
    if (t < NG*FF) g_pooled[t] = 0.0f;
}

__global__ void k_hist(const int* __restrict__ dst) {
    int e = blockIdx.x * blockDim.x + threadIdx.x;   // exactly NE threads
    atomicAdd(&g_cnt[dst[e]], 1);
}

// 3-kernel scan: per-block exclusive scan + block sums
__global__ void k_scan1() {
    __shared__ int wsum[8];
    int b = blockIdx.x, tid = threadIdx.x, lane = tid & 31, w = tid >> 5;
    int i = b * 256 + tid;
    int v = (i < NN) ? g_cnt[i] : 0;
    int inc = v;
    #pragma unroll
    for (int o = 1; o < 32; o <<= 1) {
        int nv = __shfl_up_sync(0xffffffffu, inc, o);
        if (lane >= o) inc += nv;
    }
    if (lane == 31) wsum[w] = inc;
    __syncthreads();
    if (w == 0 && lane < 8) {
        int x = wsum[lane];
        int xi = x;
        #pragma unroll
        for (int o = 1; o < 8; o <<= 1) {
            int nv = __shfl_up_sync(0xffu, xi, o, 8);
            if (lane >= o) xi += nv;
        }
        wsum[lane] = xi - x;            // exclusive warp offsets
        if (lane == 7) g_bsum[b] = xi;  // block total
    }
    __syncthreads();
    if (i < NN) g_off[i] = wsum[w] + (inc - v);
}

#define NB_SCAN 313
__global__ void k_scan2() {   // 1 block, 512 threads
    __shared__ int s[512];
    int tid = threadIdx.x;
    int v = (tid < NB_SCAN) ? g_bsum[tid] : 0;
    s[tid] = v;
    __syncthreads();
    for (int o = 1; o < 512; o <<= 1) {
        int t = (tid >= o) ? s[tid - o] : 0;
        __syncthreads();
        s[tid] += t;
        __syncthreads();
    }
    if (tid < NB_SCAN) g_boff[tid] = s[tid] - v;   // exclusive
}

__global__ void k_scan3() {
    int i = blockIdx.x * blockDim.x + threadIdx.x;
    if (i < NN) g_off[i] += g_boff[i >> 8];
    if (i == 0) g_off[NN] = NE;
}

__global__ void k_fill(const int* __restrict__ src, const int* __restrict__ dst,
                       const float* __restrict__ u) {
    int e = blockIdx.x * blockDim.x + threadIdx.x;   // exactly NE threads
    int d = dst[e];
    int pos = g_off[d] + atomicAdd(&g_cursor[d], 1);
    g_esrc[pos] = src[e];
    g_eu[pos]   = u[e];
}

// ---------------- layer 1: aggregate raw x (3-dim) then transform ----------
__global__ void k_gather3(const float* __restrict__ x) {
    int n = blockIdx.x * blockDim.x + threadIdx.x;
    if (n >= NN) return;
    int beg = g_off[n], end = g_off[n+1];
    // sums and u-weighted sums, 2 independent chains
    float sa0=0,sa1=0,sa2=0, ta0=0,ta1=0,ta2=0;
    float sb0=0,sb1=0,sb2=0, tb0=0,tb1=0,tb2=0;
    int e = beg;
    for (; e + 1 < end; e += 2) {
        int sA = __ldg(&g_esrc[e]);   float uA = __ldg(&g_eu[e]);
        int sB = __ldg(&g_esrc[e+1]); float uB = __ldg(&g_eu[e+1]);
        float xa0 = __ldg(&x[sA*3+0]), xa1 = __ldg(&x[sA*3+1]), xa2 = __ldg(&x[sA*3+2]);
        float xb0 = __ldg(&x[sB*3+0]), xb1 = __ldg(&x[sB*3+1]), xb2 = __ldg(&x[sB*3+2]);
        sa0 += xa0; sa1 += xa1; sa2 += xa2;
        ta0 += uA*xa0; ta1 += uA*xa1; ta2 += uA*xa2;
        sb0 += xb0; sb1 += xb1; sb2 += xb2;
        tb0 += uB*xb0; tb1 += uB*xb1; tb2 += uB*xb2;
    }
    if (e < end) {
        int sA = __ldg(&g_esrc[e]); float uA = __ldg(&g_eu[e]);
        float xa0 = __ldg(&x[sA*3+0]), xa1 = __ldg(&x[sA*3+1]), xa2 = __ldg(&x[sA*3+2]);
        sa0 += xa0; sa1 += xa1; sa2 += xa2;
        ta0 += uA*xa0; ta1 += uA*xa1; ta2 += uA*xa2;
    }
    float t0 = ta0+tb0, t1 = ta1+tb1, t2 = ta2+tb2;
    g_B0[n*4+0] = (sa0+sb0) - t0; g_B0[n*4+1] = (sa1+sb1) - t1; g_B0[n*4+2] = (sa2+sb2) - t2;
    g_B1[n*4+0] = t0; g_B1[n*4+1] = t1; g_B1[n*4+2] = t2;
}

__global__ void k_layer1(const float* __restrict__ x, const float* __restrict__ W,
                         const float* __restrict__ root, const float* __restrict__ b) {
    int t = blockIdx.x * blockDim.x + threadIdx.x;   // exactly NN*64 threads
    int n = t >> 6, f = t & 63;
    float agg = g_B0[n*4+0]*__ldg(&W[f])      + g_B0[n*4+1]*__ldg(&W[64+f])  + g_B0[n*4+2]*__ldg(&W[128+f])
              + g_B1[n*4+0]*__ldg(&W[192+f])  + g_B1[n*4+1]*__ldg(&W[256+f]) + g_B1[n*4+2]*__ldg(&W[320+f]);
    int dg = g_off[n+1] - g_off[n];
    float inv = 1.0f / (dg < 1 ? 1 : dg);
    float yr = x[n*3+0]*__ldg(&root[f]) + x[n*3+1]*__ldg(&root[64+f]) + x[n*3+2]*__ldg(&root[128+f]);
    g_hA[t] = elu1(agg*inv + yr + __ldg(&b[f]));
}

// ---------------- fused gather + GEMM layer (layers 2-4) -------------------
// h_out = elu( [A0*inv | A1*inv | H] @ [W0; W1; root] + b )
__global__ __launch_bounds__(256) void k_glayer(int insel, int outsel,
                                                const float* __restrict__ W,
                                                const float* __restrict__ root,
                                                const float* __restrict__ bias) {
    __shared__ float sF[64 * 192];                  // [node][A0(64)|A1(64)|H(64)]
    const float* hin  = insel  ? g_hB : g_hA;
    float*       hout = outsel ? g_hB : g_hA;
    const int nb = blockIdx.x * 64;
    const int tid = threadIdx.x;
    const int lane = tid & 31;
    const int warp = tid >> 5;                      // 0..7
    const int j = lane & 15;                        // float4 index within row
    const int half = lane >> 4;

    float4* sF4 = (float4*)sF;                      // 48 float4 per node row
    const float4* H4 = (const float4*)hin;

    // stage H rows into sF[.][128..191]
    for (int i = tid; i < 64*16; i += 256) {
        int r = i >> 4, jj = i & 15;
        sF4[r*48 + 32 + jj] = H4[(long)(nb + r)*16 + jj];
    }

    // gather: 1 warp per node, 8 nodes per warp. sum / u-weighted decomposition,
    // 2 edges in flight per half-warp.
    for (int q = 0; q < 8; ++q) {
        int n = nb + warp*8 + q;
        int beg = g_off[n], end = g_off[n+1];
        int d = end - beg;
        float inv = 1.0f / (d < 1 ? 1 : d);
        int mid = beg + ((d + 1) >> 1);
        int e0 = half ? mid : beg;
        int e1 = half ? end : mid;
        float4 sa = make_float4(0.f,0.f,0.f,0.f), ta = make_float4(0.f,0.f,0.f,0.f);
        float4 sb = make_float4(0.f,0.f,0.f,0.f), tb = make_float4(0.f,0.f,0.f,0.f);
        int e = e0;
        for (; e + 1 < e1; e += 2) {
            int  iA = __ldg(&g_esrc[e]);
            int  iB = __ldg(&g_esrc[e+1]);
            float uA = __ldg(&g_eu[e]);
            float uB = __ldg(&g_eu[e+1]);
            float4 vA = H4[(long)iA*16 + j];
            float4 vB = H4[(long)iB*16 + j];
            sa.x += vA.x; sa.y += vA.y; sa.z += vA.z; sa.w += vA.w;
            ta.x += uA*vA.x; ta.y += uA*vA.y; ta.z += uA*vA.z; ta.w += uA*vA.w;
            sb.x += vB.x; sb.y += vB.y; sb.z += vB.z; sb.w += vB.w;
            tb.x += uB*vB.x; tb.y += uB*vB.y; tb.z += uB*vB.z; tb.w += uB*vB.w;
        }
        if (e < e1) {
            int  iA = __ldg(&g_esrc[e]);
            float uA = __ldg(&g_eu[e]);
            float4 vA = H4[(long)iA*16 + j];
            sa.x += vA.x; sa.y += vA.y; sa.z += vA.z; sa.w += vA.w;
            ta.x += uA*vA.x; ta.y += uA*vA.y; ta.z += uA*vA.z; ta.w += uA*vA.w;
        }
        float4 sum, t;
        sum.x = sa.x + sb.x; sum.y = sa.y + sb.y; sum.z = sa.z + sb.z; sum.w = sa.w + sb.w;
        t.x = ta.x + tb.x; t.y = ta.y + tb.y; t.z = ta.z + tb.z; t.w = ta.w + tb.w;
        // combine halves
        sum.x += __shfl_xor_sync(0xffffffffu, sum.x, 16);
        sum.y += __shfl_xor_sync(0xffffffffu, sum.y, 16);
        sum.z += __shfl_xor_sync(0xffffffffu, sum.z, 16);
        sum.w += __shfl_xor_sync(0xffffffffu, sum.w, 16);
        t.x += __shfl_xor_sync(0xffffffffu, t.x, 16);
        t.y += __shfl_xor_sync(0xffffffffu, t.y, 16);
        t.z += __shfl_xor_sync(0xffffffffu, t.z, 16);
        t.w += __shfl_xor_sync(0xffffffffu, t.w, 16);
        int r = warp*8 + q;
        if (half == 0) {   // A0 = (sum - t) * inv
            float4 o;
            o.x = (sum.x - t.x) * inv; o.y = (sum.y - t.y) * inv;
            o.z = (sum.z - t.z) * inv; o.w = (sum.w - t.w) * inv;
            sF4[r*48 + j] = o;
        } else {           // A1 = t * inv
            float4 o;
            o.x = t.x * inv; o.y = t.y * inv; o.z = t.z * inv; o.w = t.w * inv;
            sF4[r*48 + 16 + j] = o;
        }
    }
    __syncthreads();

    // GEMM: thread tile = 4 nodes x 4 cols, k-chunks of 4 via float4
    const int f4 = tid & 15;
    const int mg = tid >> 4;

    float acc[4][4];
    #pragma unroll
    for (int i = 0; i < 4; ++i)
        #pragma unroll
        for (int c = 0; c < 4; ++c) acc[i][c] = 0.f;

    const float4* W4 = (const float4*)W;            // 128 rows (W0;W1), 16 float4/row
    const float4* R4 = (const float4*)root;         // 64 rows

    #pragma unroll 4
    for (int kc = 0; kc < 32; ++kc) {
        float4 w0 = __ldg(&W4[(4*kc+0)*16 + f4]);
        float4 w1 = __ldg(&W4[(4*kc+1)*16 + f4]);
        float4 w2 = __ldg(&W4[(4*kc+2)*16 + f4]);
        float4 w3 = __ldg(&W4[(4*kc+3)*16 + f4]);
        #pragma unroll
        for (int i = 0; i < 4; ++i) {
            int r = mg*4 + i;
            float4 xv = sF4[r*48 + kc];
            acc[i][0] += xv.x*w0.x + xv.y*w1.x + xv.z*w2.x + xv.w*w3.x;
            acc[i][1] += xv.x*w0.y + xv.y*w1.y + xv.z*w2.y + xv.w*w3.y;
            acc[i][2] += xv.x*w0.z + xv.y*w1.z + xv.z*w2.z + xv.w*w3.z;
            acc[i][3] += xv.x*w0.w + xv.y*w1.w + xv.z*w2.w + xv.w*w3.w;
        }
    }
    #pragma unroll 4
    for (int kc = 0; kc < 16; ++kc) {
        float4 w0 = __ldg(&R4[(4*kc+0)*16 + f4]);
        float4 w1 = __ldg(&R4[(4*kc+1)*16 + f4]);
        float4 w2 = __ldg(&R4[(4*kc+2)*16 + f4]);
        float4 w3 = __ldg(&R4[(4*kc+3)*16 + f4]);
        #pragma unroll
        for (int i = 0; i < 4; ++i) {
            int r = mg*4 + i;
            float4 xv = sF4[r*48 + 32 + kc];
            acc[i][0] += xv.x*w0.x + xv.y*w1.x + xv.z*w2.x + xv.w*w3.x;
            acc[i][1] += xv.x*w0.y + xv.y*w1.y + xv.z*w2.y + xv.w*w3.y;
            acc[i][2] += xv.x*w0.z + xv.y*w1.z + xv.z*w2.z + xv.w*w3.z;
            acc[i][3] += xv.x*w0.w + xv.y*w1.w + xv.z*w2.w + xv.w*w3.w;
        }
    }

    float4 bv = __ldg(&((const float4*)bias)[f4]);
    #pragma unroll
    for (int i = 0; i < 4; ++i) {
        int n = nb + mg*4 + i;
        float4 o;
        o.x = elu1(acc[i][0] + bv.x);
        o.y = elu1(acc[i][1] + bv.y);
        o.z = elu1(acc[i][2] + bv.z);
        o.w = elu1(acc[i][3] + bv.w);
        ((float4*)(hout + (long)n*64))[f4] = o;
    }
}

// ---------------- pooling ----------------
#define POOL_CHUNK 64
#define POOL_NCHUNK ((NN + POOL_CHUNK - 1) / POOL_CHUNK)   // 1250
__global__ void k_pool(const int* __restrict__ batch) {
    int t = blockIdx.x * blockDim.x + threadIdx.x;
    int j = t & 15;
    int c = t >> 4;
    if (c >= POOL_NCHUNK) return;
    int n0 = c * POOL_CHUNK;
    int n1 = n0 + POOL_CHUNK; if (n1 > NN) n1 = NN;
    const float4* h4 = (const float4*)g_hB;
    float4 acc = make_float4(0.f,0.f,0.f,0.f);
    int g = batch[n0];
    for (int n = n0; n < n1; ++n) {
        int gg = batch[n];
        if (gg != g) {
            red_add_v4(&g_pooled[g*64 + j*4], acc);
            acc = make_float4(0.f,0.f,0.f,0.f);
            g = gg;
        }
        float4 v = h4[(long)n*16 + j];
        acc.x += v.x; acc.y += v.y; acc.z += v.z; acc.w += v.w;
    }
    red_add_v4(&g_pooled[g*64 + j*4], acc);
}

// ---------------- head ----------------
__global__ void k_head(const int* __restrict__ batch, const float* __restrict__ fcw,
                       const float* __restrict__ fcb, float* __restrict__ out) {
    int g = blockIdx.x * blockDim.x + threadIdx.x;
    if (g >= NG) return;
    int lo, hi, c0, c1;
    lo = 0; hi = NN;
    while (lo < hi) { int mid = (lo + hi) >> 1; if (batch[mid] < g) lo = mid + 1; else hi = mid; }
    c0 = lo;
    lo = 0; hi = NN;
    while (lo < hi) { int mid = (lo + hi) >> 1; if (batch[mid] < g + 1) lo = mid + 1; else hi = mid; }
    c1 = lo;
    float cnt = (float)(c1 - c0);
    float inv = 1.0f / (cnt < 1.0f ? 1.0f : cnt);

    float logit[6];
    #pragma unroll
    for (int cc = 0; cc < 6; ++cc) logit[cc] = fcb[cc];
    for (int k = 0; k < 64; ++k) {
        float p = g_pooled[g*64 + k] * inv;
        #pragma unroll
        for (int cc = 0; cc < 6; ++cc) logit[cc] += p * fcw[k*6 + cc];
    }
    float m = logit[0];
    #pragma unroll
    for (int cc = 1; cc < 6; ++cc) m = fmaxf(m, logit[cc]);
    float s = 0.f;
    #pragma unroll
    for (int cc = 0; cc < 6; ++cc) s += expf(logit[cc] - m);
    float l = logf(s);
    #pragma unroll
    for (int cc = 0; cc < 6; ++cc) out[g*6 + cc] = logit[cc] - m - l;
}

// ---------------- launch ----------------
extern "C" void kernel_launch(void* const* d_in, const int* in_sizes, int n_in,
                              void* d_out, int out_size) {
    const float* x      = (const float*)d_in[0];
    const float* pseudo = (const float*)d_in[1];
    const int*   ei     = (const int*)d_in[2];
    const int*   batch  = (const int*)d_in[3];
    const float* W1 = (const float*)d_in[4];
    const float* r1 = (const float*)d_in[5];
    const float* b1 = (const float*)d_in[6];
    const float* W2 = (const float*)d_in[7];
    const float* r2 = (const float*)d_in[8];
    const float* b2 = (const float*)d_in[9];
    const float* W3 = (const float*)d_in[10];
    const float* r3 = (const float*)d_in[11];
    const float* b3 = (const float*)d_in[12];
    const float* W4 = (const float*)d_in[13];
    const float* r4 = (const float*)d_in[14];
    const float* b4 = (const float*)d_in[15];
    const float* fcw = (const float*)d_in[16];
    const float* fcb = (const float*)d_in[17];
    float* out = (float*)d_out;

    const int* src = ei;
    const int* dst = ei + NE;

    // CSR build
    k_zero<<<(NN + 255)/256, 256>>>();
    k_hist<<<NE/256, 256>>>(dst);
    k_scan1<<<NB_SCAN, 256>>>();
    k_scan2<<<1, 512>>>();
    k_scan3<<<NB_SCAN, 256>>>();
    k_fill<<<NE/256, 256>>>(src, dst, pseudo);

    // layer 1 (Fin=3)
    k_gather3<<<(NN + 255)/256, 256>>>(x);
    k_layer1<<<(NN*FF)/256, 256>>>(x, W1, r1, b1);           // -> hA

    // layers 2-4: fused gather+GEMM
    k_glayer<<<NN/64, 256>>>(0, 1, W2, r2, b2);              // hA -> hB
    k_glayer<<<NN/64, 256>>>(1, 0, W3, r3, b3);              // hB -> hA
    k_glayer<<<NN/64, 256>>>(0, 1, W4, r4, b4);              // hA -> hB

    // pooling + head
    k_pool<<<(POOL_NCHUNK*16 + 255)/256, 256>>>(batch);
    k_head<<<(NG + 255)/256, 256>>>(batch, fcw, fcb, out);
}